// round 6
// baseline (speedup 1.0000x reference)
#include <cuda_runtime.h>
#include <cstdint>
#include <cstddef>

// RNN_49297634623576: out = fc_w @ tanh(w_ih @ x[:,27,:] + b_ih + b_hh) + fc_b
// hx == 0 => w_hh unused.
//
// R6: calibrated model from R5 (L1 50.7% == predicted wavefronts exactly):
//   warps = 2048*s/R, LDS wavefronts ~ 1/R, need >=5 warps/SMSP.
// => split hidden dim ACROSS WARPS (s=4, warp stays uniform -> broadcast LDS
//    preserved, unlike R4's intra-warp split) and R=2 rows/thread.
// CTA = 4 warps x same 64 rows; warp w owns j in [16w,16w+16). Partials
// combined via conflict-free smem + 1 syncthreads + 64-thread reduce.
// 4096 warps total, ~5/SMSP resident.

#define NB   65536
#define NIN  28
#define NHID 64
#define NOUT 10
#define TPB  128   // 4 warps, 64 rows/CTA -> 1024 CTAs

typedef unsigned long long u64;

__device__ __forceinline__ u64 pk2(float a, float b) {
    u64 r; asm("mov.b64 %0,{%1,%2};" : "=l"(r) : "f"(a), "f"(b)); return r;
}
__device__ __forceinline__ void upk2(u64 v, float& a, float& b) {
    asm("mov.b64 {%0,%1},%2;" : "=f"(a), "=f"(b) : "l"(v));
}
__device__ __forceinline__ u64 ffma2(u64 a, u64 b, u64 c) {
    u64 d; asm("fma.rn.f32x2 %0,%1,%2,%3;" : "=l"(d) : "l"(a), "l"(b), "l"(c)); return d;
}
__device__ __forceinline__ u64 fadd2(u64 a, u64 b) {
    u64 d; asm("add.rn.f32x2 %0,%1,%2;" : "=l"(d) : "l"(a), "l"(b)); return d;
}
__device__ __forceinline__ float hsum2(u64 v) {
    float a, b; upk2(v, a, b); return a + b;
}

// tanh(x) = 1 - 2*rcp(exp2(x*2log2e)+1); ~1e-6 accurate.
__device__ __forceinline__ float tanh_fast(float x) {
    const float LOG2E_X2 = 2.8853900817779268f;
    float e, r;
    asm("ex2.approx.ftz.f32 %0, %1;" : "=f"(e) : "f"(x * LOG2E_X2));
    asm("rcp.approx.ftz.f32 %0, %1;" : "=f"(r) : "f"(e + 1.0f));
    return fmaf(-2.0f, r, 1.0f);
}

__global__ void __launch_bounds__(TPB, 5)
rnn_fused_kernel(const float* __restrict__ x,
                 const float* __restrict__ w_ih,
                 const float* __restrict__ b_ih,
                 const float* __restrict__ b_hh,
                 const float* __restrict__ fc_w,
                 const float* __restrict__ fc_b,
                 float* __restrict__ out)
{
    // Row j (128B): [0..13]={w[j][2p],w[j][2p+1]}, [14]={bias_j,0}, [15] pad.
    __shared__ u64 s_w[NHID][16];
    // Row j: [q<5]={fc_w[2q][j], fc_w[2q+1][j]}, [5] pad.
    __shared__ u64 s_fck[NHID][6];
    __shared__ u64 s_fcb[NOUT / 2];
    // Partials: [quarter][component][row_local]; 8B lane stride = conflict-free.
    __shared__ u64 s_part[4][NOUT / 2][64];

    const int tid = threadIdx.x;

    for (int i = tid; i < NHID * (NIN / 2); i += TPB) {
        int j = i / (NIN / 2), p = i % (NIN / 2);
        s_w[j][p] = pk2(w_ih[j * NIN + 2 * p], w_ih[j * NIN + 2 * p + 1]);
    }
    for (int i = tid; i < NHID; i += TPB) {
        s_w[i][14] = pk2(b_ih[i] + b_hh[i], 0.0f);
        s_w[i][15] = 0ull;
    }
    for (int i = tid; i < NHID * (NOUT / 2); i += TPB) {
        int j = i / (NOUT / 2), q = i % (NOUT / 2);
        s_fck[j][q] = pk2(fc_w[(2 * q) * NHID + j], fc_w[(2 * q + 1) * NHID + j]);
    }
    for (int i = tid; i < NHID; i += TPB) s_fck[i][5] = 0ull;
    if (tid < NOUT / 2) s_fcb[tid] = pk2(fc_b[2 * tid], fc_b[2 * tid + 1]);
    __syncthreads();

    const int wid   = tid >> 5;
    const int lane  = tid & 31;
    const int jbase = wid << 4;            // 16 hidden units per warp
    const int rbase = blockIdx.x << 6;     // 64 rows per CTA
    const int r0 = rbase + lane;
    const int r1 = rbase + 32 + lane;

    // Inputs for the thread's two rows (float offset 756 is 16B aligned).
    u64 in0[NIN / 2], in1[NIN / 2];
    {
        const float4* p0 = reinterpret_cast<const float4*>(x + (size_t)r0 * 784 + 756);
        const float4* p1 = reinterpret_cast<const float4*>(x + (size_t)r1 * 784 + 756);
#pragma unroll
        for (int q = 0; q < 7; q++) {
            float4 v0 = p0[q], v1 = p1[q];
            in0[2 * q]     = pk2(v0.x, v0.y);
            in0[2 * q + 1] = pk2(v0.z, v0.w);
            in1[2 * q]     = pk2(v1.x, v1.y);
            in1[2 * q + 1] = pk2(v1.z, v1.w);
        }
    }

    // FC partial accumulators {out[2q], out[2q+1]} per row; fc bias added in reduce.
    u64 oa0[NOUT / 2], oa1[NOUT / 2];
#pragma unroll
    for (int q = 0; q < NOUT / 2; q++) { oa0[q] = 0ull; oa1[q] = 0ull; }

#pragma unroll 2
    for (int jj = 0; jj < 16; jj += 2) {
        const int j0 = jbase + jj, j1 = j0 + 1;
        // 7 LDS.128 per j (uniform broadcast) + LDS.64 bias.
        const ulonglong2* rw0 = reinterpret_cast<const ulonglong2*>(&s_w[j0][0]);
        const ulonglong2* rw1 = reinterpret_cast<const ulonglong2*>(&s_w[j1][0]);
        ulonglong2 w0[7], w1[7];
#pragma unroll
        for (int p = 0; p < 7; p++) { w0[p] = rw0[p]; w1[p] = rw1[p]; }
        const u64 b0 = s_w[j0][14], b1 = s_w[j1][14];   // {bias, 0}

        // 4 independent FFMA2 chains: (j0,r0) (j0,r1) (j1,r0) (j1,r1)
        u64 a00 = b0, a01 = b0, a10 = b1, a11 = b1;
#pragma unroll
        for (int p = 0; p < 7; p++) {
            a00 = ffma2(w0[p].x, in0[2 * p], a00);
            a01 = ffma2(w0[p].x, in1[2 * p], a01);
            a10 = ffma2(w1[p].x, in0[2 * p], a10);
            a11 = ffma2(w1[p].x, in1[2 * p], a11);
            a00 = ffma2(w0[p].y, in0[2 * p + 1], a00);
            a01 = ffma2(w0[p].y, in1[2 * p + 1], a01);
            a10 = ffma2(w1[p].y, in0[2 * p + 1], a10);
            a11 = ffma2(w1[p].y, in1[2 * p + 1], a11);
        }
        float h00 = tanh_fast(hsum2(a00));
        float h01 = tanh_fast(hsum2(a01));
        float h10 = tanh_fast(hsum2(a10));
        float h11 = tanh_fast(hsum2(a11));
        u64 hp00 = pk2(h00, h00), hp01 = pk2(h01, h01);
        u64 hp10 = pk2(h10, h10), hp11 = pk2(h11, h11);

        // FC weights: 2x LDS.128 + 1x LDS.64 per j (uniform broadcast).
        const ulonglong2* rf0 = reinterpret_cast<const ulonglong2*>(&s_fck[j0][0]);
        const ulonglong2* rf1 = reinterpret_cast<const ulonglong2*>(&s_fck[j1][0]);
        ulonglong2 fA = rf0[0], fB = rf0[1];
        ulonglong2 fC = rf1[0], fD = rf1[1];
        u64 fE = s_fck[j0][4], fF = s_fck[j1][4];

        oa0[0] = ffma2(fA.x, hp00, oa0[0]);  oa1[0] = ffma2(fA.x, hp01, oa1[0]);
        oa0[1] = ffma2(fA.y, hp00, oa0[1]);  oa1[1] = ffma2(fA.y, hp01, oa1[1]);
        oa0[2] = ffma2(fB.x, hp00, oa0[2]);  oa1[2] = ffma2(fB.x, hp01, oa1[2]);
        oa0[3] = ffma2(fB.y, hp00, oa0[3]);  oa1[3] = ffma2(fB.y, hp01, oa1[3]);
        oa0[4] = ffma2(fE,   hp00, oa0[4]);  oa1[4] = ffma2(fE,   hp01, oa1[4]);
        oa0[0] = ffma2(fC.x, hp10, oa0[0]);  oa1[0] = ffma2(fC.x, hp11, oa1[0]);
        oa0[1] = ffma2(fC.y, hp10, oa0[1]);  oa1[1] = ffma2(fC.y, hp11, oa1[1]);
        oa0[2] = ffma2(fD.x, hp10, oa0[2]);  oa1[2] = ffma2(fD.x, hp11, oa1[2]);
        oa0[3] = ffma2(fD.y, hp10, oa0[3]);  oa1[3] = ffma2(fD.y, hp11, oa1[3]);
        oa0[4] = ffma2(fF,   hp10, oa0[4]);  oa1[4] = ffma2(fF,   hp11, oa1[4]);
    }

    // Publish quarter-partials (8B lane stride -> conflict-free STS.64).
#pragma unroll
    for (int c = 0; c < NOUT / 2; c++) {
        s_part[wid][c][lane]      = oa0[c];
        s_part[wid][c][lane + 32] = oa1[c];
    }
    __syncthreads();

    // Combine 4 quarters + fc bias, store. Threads 0..63 each own one row.
    if (tid < 64) {
        float2* o2 = reinterpret_cast<float2*>(out + (size_t)(rbase + tid) * NOUT);
#pragma unroll
        for (int c = 0; c < NOUT / 2; c++) {
            u64 v = fadd2(fadd2(s_part[0][c][tid], s_part[1][c][tid]),
                          fadd2(s_part[2][c][tid], s_part[3][c][tid]));
            v = fadd2(v, s_fcb[c]);
            float a, b;
            upk2(v, a, b);
            o2[c] = make_float2(a, b);
        }
    }
}

extern "C" void kernel_launch(void* const* d_in, const int* in_sizes, int n_in,
                              void* d_out, int out_size)
{
    (void)in_sizes; (void)n_in; (void)out_size;
    const float* x    = (const float*)d_in[0];
    const float* w_ih = (const float*)d_in[1];
    // d_in[2] = w_hh : unused (hx == 0)
    const float* b_ih = (const float*)d_in[3];
    const float* b_hh = (const float*)d_in[4];
    const float* fc_w = (const float*)d_in[5];
    const float* fc_b = (const float*)d_in[6];
    float* out = (float*)d_out;

    const int blocks = NB / 64;   // 1024, exact

    rnn_fused_kernel<<<blocks, TPB>>>(x, w_ih, b_ih, b_hh, fc_w, fc_b, out);
}

// round 7
// speedup vs baseline: 1.0327x; 1.0327x over previous
#include <cuda_runtime.h>
#include <cstdint>
#include <cstddef>

// RNN_49297634623576: out = fc_w @ tanh(w_ih @ x[:,27,:] + b_ih + b_hh) + fc_b
// hx == 0 => w_hh unused.
//
// R7: issue stuck at 25-31% for 512..4096 warps => binder is the per-warp
// serial sandwich LDS -> chain -> tanh(45cyc) -> FC inside each iteration.
// Fix: software pipeline. Per iteration (j-pair p):
//   [layer1(p) w/ prefetched weights] [prefetch w(p+1)] [tanh+FC(p)]
// so tanh's MUFU chain overlaps next pair's independent FFMA2s and the
// weight LDS has ~40-60cyc of covered latency. unroll 2 -> rotation renames.
// Shape kept from best round (R5): 1 row/thread, TPB=128, 512 CTAs.

#define NB   65536
#define NIN  28
#define NHID 64
#define NOUT 10
#define TPB  128   // 1 row/thread -> 512 CTAs

typedef unsigned long long u64;

__device__ __forceinline__ u64 pk2(float a, float b) {
    u64 r; asm("mov.b64 %0,{%1,%2};" : "=l"(r) : "f"(a), "f"(b)); return r;
}
__device__ __forceinline__ void upk2(u64 v, float& a, float& b) {
    asm("mov.b64 {%0,%1},%2;" : "=f"(a), "=f"(b) : "l"(v));
}
__device__ __forceinline__ u64 ffma2(u64 a, u64 b, u64 c) {
    u64 d; asm("fma.rn.f32x2 %0,%1,%2,%3;" : "=l"(d) : "l"(a), "l"(b), "l"(c)); return d;
}
__device__ __forceinline__ float hsum2(u64 v) {
    float a, b; upk2(v, a, b); return a + b;
}

// tanh(x) = 1 - 2*rcp(exp2(x*2log2e)+1); ~1e-6 accurate.
__device__ __forceinline__ float tanh_fast(float x) {
    const float LOG2E_X2 = 2.8853900817779268f;
    float e, r;
    asm("ex2.approx.ftz.f32 %0, %1;" : "=f"(e) : "f"(x * LOG2E_X2));
    asm("rcp.approx.ftz.f32 %0, %1;" : "=f"(r) : "f"(e + 1.0f));
    return fmaf(-2.0f, r, 1.0f);
}

__global__ void __launch_bounds__(TPB, 4)
rnn_fused_kernel(const float* __restrict__ x,
                 const float* __restrict__ w_ih,
                 const float* __restrict__ b_ih,
                 const float* __restrict__ b_hh,
                 const float* __restrict__ fc_w,
                 const float* __restrict__ fc_b,
                 float* __restrict__ out)
{
    // Row j (128B, 16B-aligned): [0..13]={w[j][2p],w[j][2p+1]}, [14]={bias_j,0}, [15] pad.
    __shared__ u64 s_w[NHID][16];
    // Row j: [q<5]={fc_w[2q][j], fc_w[2q+1][j]}, [5] pad.
    __shared__ u64 s_fck[NHID][6];
    __shared__ u64 s_fcb[NOUT / 2];

    const int tid = threadIdx.x;

    for (int i = tid; i < NHID * (NIN / 2); i += TPB) {
        int j = i / (NIN / 2), p = i % (NIN / 2);
        s_w[j][p] = pk2(w_ih[j * NIN + 2 * p], w_ih[j * NIN + 2 * p + 1]);
    }
    for (int i = tid; i < NHID; i += TPB) {
        s_w[i][14] = pk2(b_ih[i] + b_hh[i], 0.0f);
        s_w[i][15] = 0ull;
    }
    for (int i = tid; i < NHID * (NOUT / 2); i += TPB) {
        int j = i / (NOUT / 2), q = i % (NOUT / 2);
        s_fck[j][q] = pk2(fc_w[(2 * q) * NHID + j], fc_w[(2 * q + 1) * NHID + j]);
    }
    for (int i = tid; i < NHID; i += TPB) s_fck[i][5] = 0ull;
    if (tid < NOUT / 2) s_fcb[tid] = pk2(fc_b[2 * tid], fc_b[2 * tid + 1]);
    __syncthreads();

    const int row = blockIdx.x * TPB + tid;   // one batch row per thread

    // Last 28 floats of this row; float offset 756 is 16B aligned.
    u64 in[NIN / 2];
    {
        const float4* p = reinterpret_cast<const float4*>(x + (size_t)row * 784 + 756);
#pragma unroll
        for (int q = 0; q < 7; q++) {
            float4 v = p[q];
            in[2 * q]     = pk2(v.x, v.y);
            in[2 * q + 1] = pk2(v.z, v.w);
        }
    }

    // FC accumulators {out[2q], out[2q+1]}, fc bias pre-folded.
    u64 oa[NOUT / 2];
#pragma unroll
    for (int q = 0; q < NOUT / 2; q++) oa[q] = s_fcb[q];

    // ---- Software pipeline over 32 j-pairs ----
    // Prologue: preload weights for pair 0.
    ulonglong2 wc0[7], wc1[7];
    u64 bc0, bc1;
    {
        const ulonglong2* r0 = reinterpret_cast<const ulonglong2*>(&s_w[0][0]);
        const ulonglong2* r1 = reinterpret_cast<const ulonglong2*>(&s_w[1][0]);
#pragma unroll
        for (int q = 0; q < 7; q++) { wc0[q] = r0[q]; wc1[q] = r1[q]; }
        bc0 = s_w[0][14];
        bc1 = s_w[1][14];
    }

#pragma unroll 2
    for (int p = 0; p < 32; ++p) {
        // (1) Layer-1 for pair p using already-resident weights (2 indep chains).
        u64 a0 = bc0, a1 = bc1;
#pragma unroll
        for (int q = 0; q < 7; q++) {
            a0 = ffma2(wc0[q].x, in[2 * q], a0);
            a1 = ffma2(wc1[q].x, in[2 * q], a1);
            a0 = ffma2(wc0[q].y, in[2 * q + 1], a0);
            a1 = ffma2(wc1[q].y, in[2 * q + 1], a1);
        }

        // (2) Prefetch weights for pair p+1 (independent; covers LDS latency
        //     and pads distance between a0/a1 producers and their consumers).
        const int pn = (p + 1) & 31;
        const int jn = 2 * pn;
        ulonglong2 wn0[7], wn1[7];
        u64 bn0, bn1;
        {
            const ulonglong2* r0 = reinterpret_cast<const ulonglong2*>(&s_w[jn][0]);
            const ulonglong2* r1 = reinterpret_cast<const ulonglong2*>(&s_w[jn + 1][0]);
#pragma unroll
            for (int q = 0; q < 7; q++) { wn0[q] = r0[q]; wn1[q] = r1[q]; }
            bn0 = s_w[jn][14];
            bn1 = s_w[jn + 1][14];
        }

        // (3) tanh + FC for pair p. The tanh MUFU chains overlap (at unroll-2
        //     scope) with the next pair's layer-1 FFMA2 block.
        const int j0 = 2 * p;
        float h0 = tanh_fast(hsum2(a0));
        float h1 = tanh_fast(hsum2(a1));
        u64 hp0 = pk2(h0, h0);
        u64 hp1 = pk2(h1, h1);

        const ulonglong2* rf0 = reinterpret_cast<const ulonglong2*>(&s_fck[j0][0]);
        const ulonglong2* rf1 = reinterpret_cast<const ulonglong2*>(&s_fck[j0 + 1][0]);
        ulonglong2 fA = rf0[0], fB = rf0[1];
        ulonglong2 fC = rf1[0], fD = rf1[1];
        u64 fE = s_fck[j0][4], fF = s_fck[j0 + 1][4];

        oa[0] = ffma2(fA.x, hp0, oa[0]);
        oa[1] = ffma2(fA.y, hp0, oa[1]);
        oa[2] = ffma2(fB.x, hp0, oa[2]);
        oa[3] = ffma2(fB.y, hp0, oa[3]);
        oa[4] = ffma2(fE,   hp0, oa[4]);
        oa[0] = ffma2(fC.x, hp1, oa[0]);
        oa[1] = ffma2(fC.y, hp1, oa[1]);
        oa[2] = ffma2(fD.x, hp1, oa[2]);
        oa[3] = ffma2(fD.y, hp1, oa[3]);
        oa[4] = ffma2(fF,   hp1, oa[4]);

        // (4) Rotate prefetch buffers (renamed away under unroll 2).
#pragma unroll
        for (int q = 0; q < 7; q++) { wc0[q] = wn0[q]; wc1[q] = wn1[q]; }
        bc0 = bn0;
        bc1 = bn1;
    }

    // Store 10 floats = 5x STG.64 (40B row stride -> 8B aligned).
    {
        float2* o2 = reinterpret_cast<float2*>(out + (size_t)row * NOUT);
#pragma unroll
        for (int q = 0; q < NOUT / 2; q++) {
            float a, b;
            upk2(oa[q], a, b);
            o2[q] = make_float2(a, b);
        }
    }
}

extern "C" void kernel_launch(void* const* d_in, const int* in_sizes, int n_in,
                              void* d_out, int out_size)
{
    (void)in_sizes; (void)n_in; (void)out_size;
    const float* x    = (const float*)d_in[0];
    const float* w_ih = (const float*)d_in[1];
    // d_in[2] = w_hh : unused (hx == 0)
    const float* b_ih = (const float*)d_in[3];
    const float* b_hh = (const float*)d_in[4];
    const float* fc_w = (const float*)d_in[5];
    const float* fc_b = (const float*)d_in[6];
    float* out = (float*)d_out;

    const int blocks = NB / TPB;   // 512, exact

    rnn_fused_kernel<<<blocks, TPB>>>(x, w_ih, b_ih, b_hh, fc_w, fc_b, out);
}